// round 7
// baseline (speedup 1.0000x reference)
#include <cuda_runtime.h>
#include <cuda_bf16.h>
#include <cstdint>

#define NB 256

// Scratch: [b][mod][proj(Q,K,V)][640][100] fp32
__device__ float g_scr[196608000UL];
__device__ __nv_bfloat16 g_w_hi[6144000];
__device__ __nv_bfloat16 g_w_lo[6144000];
__device__ __nv_bfloat16 g_xt_hi[81920000UL];   // [b][l=100][c=3200]
__device__ __nv_bfloat16 g_xt_lo[81920000UL];

struct Params {
    const float* w[24];  // [mod][wq,wk,wv,bq,bk,bv]
};

// ---------------------------------------------------------------- helpers
__device__ __forceinline__ uint32_t smem_to_u32(const void* p) {
    uint32_t a;
    asm("{ .reg .u64 t; cvta.to.shared.u64 t, %1; cvt.u32.u64 %0, t; }" : "=r"(a) : "l"(p));
    return a;
}
__device__ __forceinline__ void ldsm4(uint32_t* r, uint32_t addr) {
    asm volatile("ldmatrix.sync.aligned.m8n8.x4.shared.b16 {%0,%1,%2,%3}, [%4];"
        : "=r"(r[0]), "=r"(r[1]), "=r"(r[2]), "=r"(r[3]) : "r"(addr));
}
__device__ __forceinline__ void ldsm2(uint32_t* r, uint32_t addr) {
    asm volatile("ldmatrix.sync.aligned.m8n8.x2.shared.b16 {%0,%1}, [%2];"
        : "=r"(r[0]), "=r"(r[1]) : "r"(addr));
}
__device__ __forceinline__ void mma16816(float* c, const uint32_t* a, uint32_t b0, uint32_t b1) {
    asm volatile("mma.sync.aligned.m16n8k16.row.col.f32.bf16.bf16.f32 "
        "{%0,%1,%2,%3}, {%4,%5,%6,%7}, {%8,%9}, {%0,%1,%2,%3};"
        : "+f"(c[0]), "+f"(c[1]), "+f"(c[2]), "+f"(c[3])
        : "r"(a[0]), "r"(a[1]), "r"(a[2]), "r"(a[3]), "r"(b0), "r"(b1));
}
__device__ __forceinline__ unsigned long long pack2(float x, float y) {
    unsigned long long r;
    asm("mov.b64 %0, {%1, %2};" : "=l"(r) : "f"(x), "f"(y));
    return r;
}
__device__ __forceinline__ void unpack2(unsigned long long v, float& x, float& y) {
    asm("mov.b64 {%0, %1}, %2;" : "=f"(x), "=f"(y) : "l"(v));
}
__device__ __forceinline__ void ffma2(unsigned long long& c, unsigned long long a, unsigned long long b) {
    asm("fma.rn.f32x2 %0, %1, %2, %0;" : "+l"(c) : "l"(a), "l"(b));
}
__device__ __forceinline__ unsigned long long lds_u64(uint32_t a) {
    unsigned long long v;
    asm volatile("ld.shared.b64 %0, [%1];" : "=l"(v) : "r"(a));
    return v;
}

// ============================================================================
// prep_w: fp32 weights -> bf16 hi/lo
// ============================================================================
__global__ void prep_w(Params p) {
    const int seg = blockIdx.y;
    const int mod = seg / 3;
    const int Cin = (mod == 1) ? 1280 : 640;
    const size_t offs[12] = {0, 409600, 819200, 1228800, 2048000, 2867200,
                             3686400, 4096000, 4505600, 4915200, 5324800, 5734400};
    const float* __restrict__ w = p.w[mod * 6 + (seg % 3)];
    const size_t off = offs[seg];
    const size_t n = (size_t)640 * Cin;
    for (size_t i = (size_t)blockIdx.x * blockDim.x + threadIdx.x; i < n; i += (size_t)gridDim.x * blockDim.x) {
        float v = w[i];
        __nv_bfloat16 h = __float2bfloat16(v);
        g_w_hi[off + i] = h;
        g_w_lo[off + i] = __float2bfloat16(v - __bfloat162float(h));
    }
}

// ============================================================================
// prep_x: x[b][C=3200][L=100] fp32 -> XT[b][l][c] bf16 hi/lo
// ============================================================================
__global__ void prep_x(const float* __restrict__ x) {
    __shared__ float t[32][33];
    const int b = blockIdx.z, ct = blockIdx.x, lt = blockIdx.y;
    const int tx = threadIdx.x, ty = threadIdx.y;
    const float* xb = x + (size_t)b * 320000;
    const int l = lt * 32 + tx;
    #pragma unroll
    for (int j = 0; j < 4; j++) {
        int c = ct * 32 + ty + j * 8;
        t[ty + j * 8][tx] = (l < 100) ? xb[(size_t)c * 100 + l] : 0.0f;
    }
    __syncthreads();
    const int c_out = ct * 32 + tx;
    const size_t xtb = (size_t)b * 320000;
    #pragma unroll
    for (int j = 0; j < 4; j++) {
        int lo_ = lt * 32 + ty + j * 8;
        if (lo_ < 100) {
            float v = t[tx][ty + j * 8];
            __nv_bfloat16 h = __float2bfloat16(v);
            size_t o = xtb + (size_t)lo_ * 3200 + c_out;
            g_xt_hi[o] = h;
            g_xt_lo[o] = __float2bfloat16(v - __bfloat162float(h));
        }
    }
}

// ============================================================================
// qkv_mma: Y[128,104] tile via mma.sync bf16 3-term split (ldmatrix loads).
// MMA stream interleaved t-even/t-odd for dep distance 2.
// ============================================================================
#define STAGE  37120u
#define OFF_AH 0u
#define OFF_AL 10240u
#define OFF_BH 20480u
#define OFF_BL 28800u

__global__ __launch_bounds__(256, 2) void qkv_mma(Params p) {
    extern __shared__ __align__(16) char smem_raw[];
    const uint32_t sb = smem_to_u32(smem_raw);

    const int tid = threadIdx.x;
    int bid = blockIdx.x;
    const int mtile = bid % 5; bid /= 5;
    const int proj  = bid % 3; bid /= 3;
    const int mod   = bid & 3;
    const int b     = bid >> 2;

    const int Cin = (mod == 1) ? 1280 : 640;
    const int nch = Cin >> 5;
    const int mbase = mtile * 128;

    const size_t offs[12] = {0, 409600, 819200, 1228800, 2048000, 2867200,
                             3686400, 4096000, 4505600, 4915200, 5324800, 5734400};
    const int c0m_tab[4] = {2560, 640, 1920, 0};
    const size_t woff = offs[mod * 3 + proj];
    const size_t xoff = (size_t)b * 320000 + c0m_tab[mod];
    const float* __restrict__ bias = p.w[mod * 6 + 3 + proj];
    float* __restrict__ O = g_scr + ((((size_t)b * 4 + mod) * 3 + proj) * 640 + mbase) * 100;

    const __nv_bfloat16* __restrict__ Wh = g_w_hi + woff;
    const __nv_bfloat16* __restrict__ Wl = g_w_lo + woff;
    const __nv_bfloat16* __restrict__ Xh = g_xt_hi + xoff;
    const __nv_bfloat16* __restrict__ Xl = g_xt_lo + xoff;

    for (int idx = tid; idx < 320; idx += 256) {
        int st = idx / 160, rest = idx % 160;
        int buf = rest / 80, r2 = rest % 80;
        uint32_t a = sb + (uint32_t)st * STAGE + (buf ? OFF_BL : OFF_BH)
                   + (uint32_t)(100 + r2 / 20) * 80 + (uint32_t)(r2 % 20) * 4;
        asm volatile("st.shared.b32 [%0], %1;" :: "r"(a), "r"(0) : "memory");
    }

    auto issue_chunk = [&](int st, int c) {
        const int k0 = c << 5;
        const uint32_t stg = sb + (uint32_t)st * STAGE;
        for (int idx = tid; idx < 1824; idx += 256) {
            const __nv_bfloat16* src;
            uint32_t dst;
            if (idx < 1024) {
                int buf = idx >> 9, r = (idx >> 2) & 127, seg = idx & 3;
                src = (buf ? Wl : Wh) + (size_t)(mbase + r) * Cin + k0 + seg * 8;
                dst = stg + (buf ? OFF_AL : OFF_AH) + (uint32_t)r * 80 + (uint32_t)seg * 16;
            } else {
                int j = idx - 1024;
                int n = j >> 3, rem = j & 7;
                int buf = rem >> 2, seg = rem & 3;
                src = (buf ? Xl : Xh) + (size_t)n * 3200 + k0 + seg * 8;
                dst = stg + (buf ? OFF_BL : OFF_BH) + (uint32_t)n * 80 + (uint32_t)seg * 16;
            }
            asm volatile("cp.async.cg.shared.global [%0], [%1], 16;" :: "r"(dst), "l"(src) : "memory");
        }
        asm volatile("cp.async.commit_group;" ::: "memory");
    };

    const int w = tid >> 5, lane = tid & 31;
    const int rloc = w * 16 + (lane >> 2);
    const int qd = lane & 3;

    const uint32_t aoff = (uint32_t)(w * 16 + (lane & 15)) * 80 + (uint32_t)(lane >> 4) * 16;
    const uint32_t b4off = (uint32_t)(((lane >> 4) * 8) + (lane & 7)) * 80 + (uint32_t)((lane >> 3) & 1) * 16;
    const uint32_t b2off = (uint32_t)(lane & 7) * 80 + (uint32_t)((lane >> 3) & 1) * 16;

    float acc[13][4];
    #pragma unroll
    for (int t = 0; t < 13; t++)
        #pragma unroll
        for (int i = 0; i < 4; i++) acc[t][i] = 0.0f;

    issue_chunk(0, 0);

    for (int c = 0; c < nch; c++) {
        const int s = c & 1;
        if (c + 1 < nch) {
            issue_chunk(s ^ 1, c + 1);
            asm volatile("cp.async.wait_group 1;" ::: "memory");
        } else {
            asm volatile("cp.async.wait_group 0;" ::: "memory");
        }
        __syncthreads();

        const uint32_t stg = sb + (uint32_t)s * STAGE;
        const uint32_t aAh = stg + OFF_AH + aoff;
        const uint32_t aAl = stg + OFF_AL + aoff;
        const uint32_t aBh4 = stg + OFF_BH + b4off;
        const uint32_t aBl4 = stg + OFF_BL + b4off;
        const uint32_t aBh2 = stg + OFF_BH + 7680u + b2off;
        const uint32_t aBl2 = stg + OFF_BL + 7680u + b2off;

        #pragma unroll
        for (int s16 = 0; s16 < 2; s16++) {
            const uint32_t ko = (uint32_t)s16 * 32;
            uint32_t ah[4], al[4];
            ldsm4(ah, aAh + ko);
            ldsm4(al, aAl + ko);
            #pragma unroll
            for (int pr = 0; pr < 6; pr++) {
                uint32_t bh[4], bl[4];
                ldsm4(bh, aBh4 + (uint32_t)pr * 1280 + ko);
                ldsm4(bl, aBl4 + (uint32_t)pr * 1280 + ko);
                // interleaved: dep distance 2 on each accumulator
                mma16816(acc[2 * pr],     ah, bh[0], bh[1]);
                mma16816(acc[2 * pr + 1], ah, bh[2], bh[3]);
                mma16816(acc[2 * pr],     ah, bl[0], bl[1]);
                mma16816(acc[2 * pr + 1], ah, bl[2], bl[3]);
                mma16816(acc[2 * pr],     al, bh[0], bh[1]);
                mma16816(acc[2 * pr + 1], al, bh[2], bh[3]);
            }
            {
                uint32_t bh[2], bl[2];
                ldsm2(bh, aBh2 + ko);
                ldsm2(bl, aBl2 + ko);
                mma16816(acc[12], ah, bh[0], bh[1]);
                mma16816(acc[12], ah, bl[0], bl[1]);
                mma16816(acc[12], al, bh[0], bh[1]);
            }
        }
        __syncthreads();
    }

    const float bv0 = bias[mbase + rloc];
    const float bv1 = bias[mbase + rloc + 8];
    float* o0 = O + (size_t)rloc * 100;
    float* o1 = o0 + 800;
    #pragma unroll
    for (int t = 0; t < 13; t++) {
        int col = t * 8 + qd * 2;
        if (col < 100) {
            float2 v0 = make_float2(acc[t][0] + bv0, acc[t][1] + bv0);
            float2 v1 = make_float2(acc[t][2] + bv1, acc[t][3] + bv1);
            *(float2*)(o0 + col) = v0;
            *(float2*)(o1 + col) = v1;
        }
    }
}

// ============================================================================
// Pass 2: attention.  Retiled for b64 smem loads.
//   Phase A: thread tile 1l x 20m, f32x2 accumulators packed over m pairs.
//   Phase C: j contracted in pairs via b64 loads of V and P rows.
// ============================================================================
__global__ __launch_bounds__(256) void attn_kernel(float* __restrict__ out) {
    const int tid = threadIdx.x;
    int bid = blockIdx.x;
    const int half = bid & 1;
    const int bm   = bid >> 1;
    const int mod  = bm & 3;
    const int b    = bm >> 2;

    const float* __restrict__ Q = g_scr + (size_t)bm * 3 * 64000;
    const float* __restrict__ K = Q + 64000;
    const float* __restrict__ V = Q + 128000;
    float* __restrict__ O = out + ((size_t)mod * NB + b) * 64000;

    __shared__ __align__(16) float Ss[50][102];   // stride 102 (even) for b64 loads
    __shared__ __align__(16) float u[4864];       // Qc[32][52] | Kc[32][100]  / Vc[40][102]

    const uint32_t u_b = smem_to_u32(u);
    const uint32_t ss_b = smem_to_u32(Ss);

    // ---- Phase A: S = Q^T K over k-chunks of 32; tile 1l x 20m ----
    const bool act = tid < 250;
    const int l0 = tid % 50, mg = tid / 50;   // mg 0..4
    const int m0 = mg * 20;
    const int colQ = half * 50;

    unsigned long long sacc[10];  // sacc[j] = (S[l0][m0+2j], S[l0][m0+2j+1])
    #pragma unroll
    for (int j = 0; j < 10; j++) sacc[j] = 0ULL;

    for (int c0 = 0; c0 < 640; c0 += 32) {
        for (int idx = tid; idx < 800; idx += 256) {       // Qc: 32 x 50 (float2)
            int row = idx / 25, c2 = (idx % 25) * 2;
            *(float2*)&u[row * 52 + c2] = *(const float2*)(Q + (size_t)(c0 + row) * 100 + colQ + c2);
        }
        for (int idx = tid; idx < 800; idx += 256) {       // Kc: 32 x 100 (float4)
            int row = idx / 25, c4 = (idx % 25) * 4;
            *(float4*)&u[1664 + row * 100 + c4] = *(const float4*)(K + (size_t)(c0 + row) * 100 + c4);
        }
        __syncthreads();
        if (act) {
            #pragma unroll 4
            for (int kk = 0; kk < 32; kk++) {
                float qv = u[kk * 52 + l0];
                unsigned long long qp = pack2(qv, qv);
                const uint32_t kb = u_b + (uint32_t)(1664 + kk * 100 + m0) * 4;
                #pragma unroll
                for (int j = 0; j < 10; j++) {
                    ffma2(sacc[j], qp, lds_u64(kb + (uint32_t)j * 8));
                }
            }
        }
        __syncthreads();
    }
    if (act) {
        #pragma unroll
        for (int j = 0; j < 10; j++) {
            float lo, hi;
            unpack2(sacc[j], lo, hi);
            *(float2*)&Ss[l0][m0 + 2 * j] = make_float2(lo, hi);
        }
    }
    __syncthreads();

    // ---- Phase B: softmax over 100 cols, rows 0..49 ----
    {
        const int warp = tid >> 5, lane = tid & 31;
        for (int r = warp; r < 50; r += 8) {
            float v0 = Ss[r][lane];
            float v1 = Ss[r][lane + 32];
            float v2 = Ss[r][lane + 64];
            float v3 = (lane < 4) ? Ss[r][lane + 96] : -3.4e38f;
            float mx = fmaxf(fmaxf(v0, v1), fmaxf(v2, v3));
            #pragma unroll
            for (int o = 16; o; o >>= 1) mx = fmaxf(mx, __shfl_xor_sync(0xffffffffu, mx, o));
            v0 = __expf(v0 - mx);
            v1 = __expf(v1 - mx);
            v2 = __expf(v2 - mx);
            v3 = (lane < 4) ? __expf(v3 - mx) : 0.0f;
            float s = v0 + v1 + v2 + v3;
            #pragma unroll
            for (int o = 16; o; o >>= 1) s += __shfl_xor_sync(0xffffffffu, s, o);
            float inv = 1.0f / s;
            Ss[r][lane]      = v0 * inv;
            Ss[r][lane + 32] = v1 * inv;
            Ss[r][lane + 64] = v2 * inv;
            if (lane < 4) Ss[r][lane + 96] = v3 * inv;
        }
    }

    // ---- Phase C: O = V @ P^T, V chunks of 40 rows (Vc stride 102) ----
    const int cg = tid % 10, ig = tid / 10;
    const bool actC = tid < 250;
    const int cl0 = cg * 4, i0 = ig * 2;

    for (int chunk = 0; chunk < 16; chunk++) {
        __syncthreads();
        for (int idx = tid; idx < 1000; idx += 256) {
            int row = idx / 25, c4 = (idx % 25) * 4;
            float4 v = *(const float4*)(V + (size_t)(chunk * 40 + row) * 100 + c4);
            u[row * 102 + c4 + 0] = v.x;
            u[row * 102 + c4 + 1] = v.y;
            u[row * 102 + c4 + 2] = v.z;
            u[row * 102 + c4 + 3] = v.w;
        }
        __syncthreads();
        if (actC) {
            unsigned long long pacc[4][2];
            #pragma unroll
            for (int uu = 0; uu < 4; uu++) { pacc[uu][0] = 0ULL; pacc[uu][1] = 0ULL; }
            const uint32_t pa_b = ss_b + (uint32_t)(i0 * 102) * 4;
            const uint32_t pb_b = pa_b + 408u;
            const uint32_t v_b = u_b + (uint32_t)(cl0 * 102) * 4;
            #pragma unroll 5
            for (int j2 = 0; j2 < 50; j2++) {
                unsigned long long pap = lds_u64(pa_b + (uint32_t)j2 * 8);
                unsigned long long pbp = lds_u64(pb_b + (uint32_t)j2 * 8);
                #pragma unroll
                for (int uu = 0; uu < 4; uu++) {
                    unsigned long long vv = lds_u64(v_b + (uint32_t)uu * 408u + (uint32_t)j2 * 8);
                    ffma2(pacc[uu][0], vv, pap);
                    ffma2(pacc[uu][1], vv, pbp);
                }
            }
            #pragma unroll
            for (int uu = 0; uu < 4; uu++) {
                float x0, y0, x1, y1;
                unpack2(pacc[uu][0], x0, y0);
                unpack2(pacc[uu][1], x1, y1);
                int c = chunk * 40 + cl0 + uu;
                O[(size_t)c * 100 + half * 50 + i0]     = x0 + y0;
                O[(size_t)c * 100 + half * 50 + i0 + 1] = x1 + y1;
            }
        }
    }
}

extern "C" void kernel_launch(void* const* d_in, const int* in_sizes, int n_in,
                              void* d_out, int out_size) {
    const float* x = (const float*)d_in[0];
    Params p;
    for (int i = 0; i < 24; i++) p.w[i] = (const float*)d_in[1 + i];

    prep_w<<<dim3(800, 12), 256>>>(p);
    prep_x<<<dim3(100, 4, 256), dim3(32, 8)>>>(x);

    cudaFuncSetAttribute(qkv_mma, cudaFuncAttributeMaxDynamicSharedMemorySize, 74240);
    qkv_mma<<<15360, 256, 74240>>>(p);

    attn_kernel<<<2048, 256>>>((float*)d_out);
}

// round 8
// speedup vs baseline: 1.2037x; 1.2037x over previous
#include <cuda_runtime.h>
#include <cuda_bf16.h>
#include <cstdint>

#define NB 256

// Scratch: [b][mod][proj(Q,K,V)][640][100] fp32
__device__ float g_scr[196608000UL];
__device__ __nv_bfloat16 g_w_hi[6144000];
__device__ __nv_bfloat16 g_w_lo[6144000];
__device__ __nv_bfloat16 g_xt_hi[81920000UL];   // [b][l=100][c=3200]
__device__ __nv_bfloat16 g_xt_lo[81920000UL];

struct Params {
    const float* w[24];  // [mod][wq,wk,wv,bq,bk,bv]
};

// ---------------------------------------------------------------- helpers
__device__ __forceinline__ uint32_t smem_to_u32(const void* p) {
    uint32_t a;
    asm("{ .reg .u64 t; cvta.to.shared.u64 t, %1; cvt.u32.u64 %0, t; }" : "=r"(a) : "l"(p));
    return a;
}
__device__ __forceinline__ void ldsm4(uint32_t* r, uint32_t addr) {
    asm volatile("ldmatrix.sync.aligned.m8n8.x4.shared.b16 {%0,%1,%2,%3}, [%4];"
        : "=r"(r[0]), "=r"(r[1]), "=r"(r[2]), "=r"(r[3]) : "r"(addr));
}
__device__ __forceinline__ void ldsm2(uint32_t* r, uint32_t addr) {
    asm volatile("ldmatrix.sync.aligned.m8n8.x2.shared.b16 {%0,%1}, [%2];"
        : "=r"(r[0]), "=r"(r[1]) : "r"(addr));
}
__device__ __forceinline__ void mma16816(float* c, const uint32_t* a, uint32_t b0, uint32_t b1) {
    asm volatile("mma.sync.aligned.m16n8k16.row.col.f32.bf16.bf16.f32 "
        "{%0,%1,%2,%3}, {%4,%5,%6,%7}, {%8,%9}, {%0,%1,%2,%3};"
        : "+f"(c[0]), "+f"(c[1]), "+f"(c[2]), "+f"(c[3])
        : "r"(a[0]), "r"(a[1]), "r"(a[2]), "r"(a[3]), "r"(b0), "r"(b1));
}
__device__ __forceinline__ unsigned long long pack2(float x, float y) {
    unsigned long long r;
    asm("mov.b64 %0, {%1, %2};" : "=l"(r) : "f"(x), "f"(y));
    return r;
}
__device__ __forceinline__ void unpack2(unsigned long long v, float& x, float& y) {
    asm("mov.b64 {%0, %1}, %2;" : "=f"(x), "=f"(y) : "l"(v));
}
__device__ __forceinline__ void ffma2(unsigned long long& c, unsigned long long a, unsigned long long b) {
    asm("fma.rn.f32x2 %0, %1, %2, %0;" : "+l"(c) : "l"(a), "l"(b));
}
__device__ __forceinline__ unsigned long long lds_u64(uint32_t a) {
    unsigned long long v;
    asm volatile("ld.shared.b64 %0, [%1];" : "=l"(v) : "r"(a));
    return v;
}

// ============================================================================
// prep_w: fp32 weights -> bf16 hi/lo
// ============================================================================
__global__ void prep_w(Params p) {
    const int seg = blockIdx.y;
    const int mod = seg / 3;
    const int Cin = (mod == 1) ? 1280 : 640;
    const size_t offs[12] = {0, 409600, 819200, 1228800, 2048000, 2867200,
                             3686400, 4096000, 4505600, 4915200, 5324800, 5734400};
    const float* __restrict__ w = p.w[mod * 6 + (seg % 3)];
    const size_t off = offs[seg];
    const size_t n = (size_t)640 * Cin;
    for (size_t i = (size_t)blockIdx.x * blockDim.x + threadIdx.x; i < n; i += (size_t)gridDim.x * blockDim.x) {
        float v = w[i];
        __nv_bfloat16 h = __float2bfloat16(v);
        g_w_hi[off + i] = h;
        g_w_lo[off + i] = __float2bfloat16(v - __bfloat162float(h));
    }
}

// ============================================================================
// prep_x: x[b][C=3200][L=100] fp32 -> XT[b][l][c] bf16 hi/lo
// ============================================================================
__global__ void prep_x(const float* __restrict__ x) {
    __shared__ float t[32][33];
    const int b = blockIdx.z, ct = blockIdx.x, lt = blockIdx.y;
    const int tx = threadIdx.x, ty = threadIdx.y;
    const float* xb = x + (size_t)b * 320000;
    const int l = lt * 32 + tx;
    #pragma unroll
    for (int j = 0; j < 4; j++) {
        int c = ct * 32 + ty + j * 8;
        t[ty + j * 8][tx] = (l < 100) ? xb[(size_t)c * 100 + l] : 0.0f;
    }
    __syncthreads();
    const int c_out = ct * 32 + tx;
    const size_t xtb = (size_t)b * 320000;
    #pragma unroll
    for (int j = 0; j < 4; j++) {
        int lo_ = lt * 32 + ty + j * 8;
        if (lo_ < 100) {
            float v = t[tx][ty + j * 8];
            __nv_bfloat16 h = __float2bfloat16(v);
            size_t o = xtb + (size_t)lo_ * 3200 + c_out;
            g_xt_hi[o] = h;
            g_xt_lo[o] = __float2bfloat16(v - __bfloat162float(h));
        }
    }
}

// ============================================================================
// qkv_mma: unchanged from R7 (measured neutral vs R6).
// ============================================================================
#define STAGE  37120u
#define OFF_AH 0u
#define OFF_AL 10240u
#define OFF_BH 20480u
#define OFF_BL 28800u

__global__ __launch_bounds__(256, 2) void qkv_mma(Params p) {
    extern __shared__ __align__(16) char smem_raw[];
    const uint32_t sb = smem_to_u32(smem_raw);

    const int tid = threadIdx.x;
    int bid = blockIdx.x;
    const int mtile = bid % 5; bid /= 5;
    const int proj  = bid % 3; bid /= 3;
    const int mod   = bid & 3;
    const int b     = bid >> 2;

    const int Cin = (mod == 1) ? 1280 : 640;
    const int nch = Cin >> 5;
    const int mbase = mtile * 128;

    const size_t offs[12] = {0, 409600, 819200, 1228800, 2048000, 2867200,
                             3686400, 4096000, 4505600, 4915200, 5324800, 5734400};
    const int c0m_tab[4] = {2560, 640, 1920, 0};
    const size_t woff = offs[mod * 3 + proj];
    const size_t xoff = (size_t)b * 320000 + c0m_tab[mod];
    const float* __restrict__ bias = p.w[mod * 6 + 3 + proj];
    float* __restrict__ O = g_scr + ((((size_t)b * 4 + mod) * 3 + proj) * 640 + mbase) * 100;

    const __nv_bfloat16* __restrict__ Wh = g_w_hi + woff;
    const __nv_bfloat16* __restrict__ Wl = g_w_lo + woff;
    const __nv_bfloat16* __restrict__ Xh = g_xt_hi + xoff;
    const __nv_bfloat16* __restrict__ Xl = g_xt_lo + xoff;

    for (int idx = tid; idx < 320; idx += 256) {
        int st = idx / 160, rest = idx % 160;
        int buf = rest / 80, r2 = rest % 80;
        uint32_t a = sb + (uint32_t)st * STAGE + (buf ? OFF_BL : OFF_BH)
                   + (uint32_t)(100 + r2 / 20) * 80 + (uint32_t)(r2 % 20) * 4;
        asm volatile("st.shared.b32 [%0], %1;" :: "r"(a), "r"(0) : "memory");
    }

    auto issue_chunk = [&](int st, int c) {
        const int k0 = c << 5;
        const uint32_t stg = sb + (uint32_t)st * STAGE;
        for (int idx = tid; idx < 1824; idx += 256) {
            const __nv_bfloat16* src;
            uint32_t dst;
            if (idx < 1024) {
                int buf = idx >> 9, r = (idx >> 2) & 127, seg = idx & 3;
                src = (buf ? Wl : Wh) + (size_t)(mbase + r) * Cin + k0 + seg * 8;
                dst = stg + (buf ? OFF_AL : OFF_AH) + (uint32_t)r * 80 + (uint32_t)seg * 16;
            } else {
                int j = idx - 1024;
                int n = j >> 3, rem = j & 7;
                int buf = rem >> 2, seg = rem & 3;
                src = (buf ? Xl : Xh) + (size_t)n * 3200 + k0 + seg * 8;
                dst = stg + (buf ? OFF_BL : OFF_BH) + (uint32_t)n * 80 + (uint32_t)seg * 16;
            }
            asm volatile("cp.async.cg.shared.global [%0], [%1], 16;" :: "r"(dst), "l"(src) : "memory");
        }
        asm volatile("cp.async.commit_group;" ::: "memory");
    };

    const int w = tid >> 5, lane = tid & 31;
    const int rloc = w * 16 + (lane >> 2);
    const int qd = lane & 3;

    const uint32_t aoff = (uint32_t)(w * 16 + (lane & 15)) * 80 + (uint32_t)(lane >> 4) * 16;
    const uint32_t b4off = (uint32_t)(((lane >> 4) * 8) + (lane & 7)) * 80 + (uint32_t)((lane >> 3) & 1) * 16;
    const uint32_t b2off = (uint32_t)(lane & 7) * 80 + (uint32_t)((lane >> 3) & 1) * 16;

    float acc[13][4];
    #pragma unroll
    for (int t = 0; t < 13; t++)
        #pragma unroll
        for (int i = 0; i < 4; i++) acc[t][i] = 0.0f;

    issue_chunk(0, 0);

    for (int c = 0; c < nch; c++) {
        const int s = c & 1;
        if (c + 1 < nch) {
            issue_chunk(s ^ 1, c + 1);
            asm volatile("cp.async.wait_group 1;" ::: "memory");
        } else {
            asm volatile("cp.async.wait_group 0;" ::: "memory");
        }
        __syncthreads();

        const uint32_t stg = sb + (uint32_t)s * STAGE;
        const uint32_t aAh = stg + OFF_AH + aoff;
        const uint32_t aAl = stg + OFF_AL + aoff;
        const uint32_t aBh4 = stg + OFF_BH + b4off;
        const uint32_t aBl4 = stg + OFF_BL + b4off;
        const uint32_t aBh2 = stg + OFF_BH + 7680u + b2off;
        const uint32_t aBl2 = stg + OFF_BL + 7680u + b2off;

        #pragma unroll
        for (int s16 = 0; s16 < 2; s16++) {
            const uint32_t ko = (uint32_t)s16 * 32;
            uint32_t ah[4], al[4];
            ldsm4(ah, aAh + ko);
            ldsm4(al, aAl + ko);
            #pragma unroll
            for (int pr = 0; pr < 6; pr++) {
                uint32_t bh[4], bl[4];
                ldsm4(bh, aBh4 + (uint32_t)pr * 1280 + ko);
                ldsm4(bl, aBl4 + (uint32_t)pr * 1280 + ko);
                mma16816(acc[2 * pr],     ah, bh[0], bh[1]);
                mma16816(acc[2 * pr + 1], ah, bh[2], bh[3]);
                mma16816(acc[2 * pr],     ah, bl[0], bl[1]);
                mma16816(acc[2 * pr + 1], ah, bl[2], bl[3]);
                mma16816(acc[2 * pr],     al, bh[0], bh[1]);
                mma16816(acc[2 * pr + 1], al, bh[2], bh[3]);
            }
            {
                uint32_t bh[2], bl[2];
                ldsm2(bh, aBh2 + ko);
                ldsm2(bl, aBl2 + ko);
                mma16816(acc[12], ah, bh[0], bh[1]);
                mma16816(acc[12], ah, bl[0], bl[1]);
                mma16816(acc[12], al, bh[0], bh[1]);
            }
        }
        __syncthreads();
    }

    const float bv0 = bias[mbase + rloc];
    const float bv1 = bias[mbase + rloc + 8];
    float* o0 = O + (size_t)rloc * 100;
    float* o1 = o0 + 800;
    #pragma unroll
    for (int t = 0; t < 13; t++) {
        int col = t * 8 + qd * 2;
        if (col < 100) {
            float2 v0 = make_float2(acc[t][0] + bv0, acc[t][1] + bv0);
            float2 v1 = make_float2(acc[t][2] + bv1, acc[t][3] + bv1);
            *(float2*)(o0 + col) = v0;
            *(float2*)(o1 + col) = v1;
        }
    }
}

// ============================================================================
// Pass 2: attention v3.  One CTA per (b,mod), grid 1024, 256 threads.
// Smem: Ss[100][104] | Pt[100][102] (P transposed) | U (Qc/Kc, aliased Vc)
//   Phase A: 4l x 10m tile, m-packed f32x2, conflict-free loads
//   Phase B: softmax + transposed write to Pt
//   Phase C: 4c x 4i tile, i-packed f32x2 with b64 Pt loads
// ============================================================================
#define SS_OFF 0
#define PT_OFF 10400
#define U_OFF  20600
#define KC_OFF 3328        // within U (words)
#define ATTN_SMEM 109024   // (10400 + 10200 + 6656) * 4

__global__ __launch_bounds__(256) void attn_kernel(float* __restrict__ out) {
    extern __shared__ __align__(16) float sm[];
    const int tid = threadIdx.x;
    const int bm = blockIdx.x;           // b*4 + mod
    const int mod = bm & 3, b = bm >> 2;

    const float* __restrict__ Q = g_scr + (size_t)bm * 192000;
    const float* __restrict__ K = Q + 64000;
    const float* __restrict__ V = Q + 128000;
    float* __restrict__ O = out + ((size_t)mod * NB + b) * 64000;

    float* Ss = sm + SS_OFF;             // stride 104
    float* Pt = sm + PT_OFF;             // stride 102
    float* U  = sm + U_OFF;              // Qc stride 104; Kc at +KC_OFF stride 104; Vc stride 100
    const uint32_t u_b = smem_to_u32(U);
    const uint32_t pt_b = smem_to_u32(Pt);

    // ---- Phase A: S[100,100] = Q^T K, k-chunks of 32 ----
    const bool act = tid < 250;
    const int lg = tid % 25;             // l set {lg, lg+25, lg+50, lg+75}
    const int mg = tid / 25;             // 0..9 active
    const int m0 = mg * 10;

    unsigned long long acc[4][5];        // acc[t][j] = (S[l][m0+2j], S[l][m0+2j+1])
    #pragma unroll
    for (int t = 0; t < 4; t++)
        #pragma unroll
        for (int j = 0; j < 5; j++) acc[t][j] = 0ULL;

    for (int c0 = 0; c0 < 640; c0 += 32) {
        for (int idx = tid; idx < 1600; idx += 256) {
            int which = idx >= 800;
            int i2 = idx - which * 800;
            int row = i2 / 25, c4 = (i2 % 25) * 4;
            const float* src = (which ? K : Q) + (size_t)(c0 + row) * 100 + c4;
            *(float4*)(U + which * KC_OFF + row * 104 + c4) = *(const float4*)src;
        }
        __syncthreads();
        if (act) {
            #pragma unroll 2
            for (int kk = 0; kk < 32; kk++) {
                const float* qrow = U + kk * 104;
                unsigned long long qd[4];
                #pragma unroll
                for (int t = 0; t < 4; t++) {
                    float qv = qrow[lg + 25 * t];
                    qd[t] = pack2(qv, qv);
                }
                const uint32_t kb = u_b + (uint32_t)(KC_OFF + kk * 104 + m0) * 4;
                #pragma unroll
                for (int j = 0; j < 5; j++) {
                    unsigned long long kv = lds_u64(kb + (uint32_t)j * 8);
                    ffma2(acc[0][j], qd[0], kv);
                    ffma2(acc[1][j], qd[1], kv);
                    ffma2(acc[2][j], qd[2], kv);
                    ffma2(acc[3][j], qd[3], kv);
                }
            }
        }
        __syncthreads();
    }
    if (act) {
        #pragma unroll
        for (int t = 0; t < 4; t++)
            #pragma unroll
            for (int j = 0; j < 5; j++) {
                float lo, hi;
                unpack2(acc[t][j], lo, hi);
                *(float2*)&Ss[(lg + 25 * t) * 104 + m0 + 2 * j] = make_float2(lo, hi);
            }
    }
    __syncthreads();

    // ---- Phase B: softmax rows 0..99, write transposed to Pt[j][i] ----
    {
        const int warp = tid >> 5, lane = tid & 31;
        for (int r = warp; r < 100; r += 8) {
            const float* srow = Ss + r * 104;
            float v0 = srow[lane];
            float v1 = srow[lane + 32];
            float v2 = srow[lane + 64];
            float v3 = (lane < 4) ? srow[lane + 96] : -3.4e38f;
            float mx = fmaxf(fmaxf(v0, v1), fmaxf(v2, v3));
            #pragma unroll
            for (int o = 16; o; o >>= 1) mx = fmaxf(mx, __shfl_xor_sync(0xffffffffu, mx, o));
            v0 = __expf(v0 - mx);
            v1 = __expf(v1 - mx);
            v2 = __expf(v2 - mx);
            v3 = (lane < 4) ? __expf(v3 - mx) : 0.0f;
            float s = v0 + v1 + v2 + v3;
            #pragma unroll
            for (int o = 16; o; o >>= 1) s += __shfl_xor_sync(0xffffffffu, s, o);
            float inv = 1.0f / s;
            Pt[lane * 102 + r]        = v0 * inv;
            Pt[(lane + 32) * 102 + r] = v1 * inv;
            Pt[(lane + 64) * 102 + r] = v2 * inv;
            if (lane < 4) Pt[(lane + 96) * 102 + r] = v3 * inv;
        }
    }

    // ---- Phase C: O[640,100] = V @ P^T, V chunks of 40 rows ----
    const int cg = tid % 10, ig = tid / 10;  // ig 0..24 active
    const bool actC = tid < 250;
    const int i0 = ig * 4;

    for (int chunk = 0; chunk < 16; chunk++) {
        __syncthreads();                     // softmax done / prior Vc consumers done
        for (int idx = tid; idx < 1000; idx += 256) {
            int row = idx / 25, c4 = (idx % 25) * 4;
            *(float4*)(U + row * 100 + c4) =
                *(const float4*)(V + (size_t)(chunk * 40 + row) * 100 + c4);
        }
        __syncthreads();
        if (actC) {
            unsigned long long pacc[4][2];
            #pragma unroll
            for (int u = 0; u < 4; u++) { pacc[u][0] = 0ULL; pacc[u][1] = 0ULL; }
            const uint32_t pb = pt_b + (uint32_t)i0 * 4;
            #pragma unroll 4
            for (int j = 0; j < 100; j++) {
                unsigned long long pp0 = lds_u64(pb + (uint32_t)j * 408);
                unsigned long long pp1 = lds_u64(pb + (uint32_t)j * 408 + 8);
                #pragma unroll
                for (int u = 0; u < 4; u++) {
                    float vv = U[(cg + 10 * u) * 100 + j];   // c spread {cg,+10,+20,+30}
                    unsigned long long vd = pack2(vv, vv);
                    ffma2(pacc[u][0], vd, pp0);
                    ffma2(pacc[u][1], vd, pp1);
                }
            }
            #pragma unroll
            for (int u = 0; u < 4; u++) {
                float a0, a1, a2, a3;
                unpack2(pacc[u][0], a0, a1);
                unpack2(pacc[u][1], a2, a3);
                int c_ = chunk * 40 + cg + 10 * u;
                *(float4*)&O[(size_t)c_ * 100 + i0] = make_float4(a0, a1, a2, a3);
            }
        }
    }
}

extern "C" void kernel_launch(void* const* d_in, const int* in_sizes, int n_in,
                              void* d_out, int out_size) {
    const float* x = (const float*)d_in[0];
    Params p;
    for (int i = 0; i < 24; i++) p.w[i] = (const float*)d_in[1 + i];

    prep_w<<<dim3(800, 12), 256>>>(p);
    prep_x<<<dim3(100, 4, 256), dim3(32, 8)>>>(x);

    cudaFuncSetAttribute(qkv_mma, cudaFuncAttributeMaxDynamicSharedMemorySize, 74240);
    qkv_mma<<<15360, 256, 74240>>>(p);

    cudaFuncSetAttribute(attn_kernel, cudaFuncAttributeMaxDynamicSharedMemorySize, ATTN_SMEM);
    attn_kernel<<<1024, 256, ATTN_SMEM>>>((float*)d_out);
}

// round 9
// speedup vs baseline: 1.2744x; 1.0587x over previous
#include <cuda_runtime.h>
#include <cuda_bf16.h>
#include <cstdint>

#define NB 256

// Scratch: [b][mod][proj(Q,K,V)][640][100] fp32
__device__ float g_scr[196608000UL];
__device__ __nv_bfloat16 g_w_hi[6144000];
__device__ __nv_bfloat16 g_w_lo[6144000];
__device__ __nv_bfloat16 g_xt_hi[81920000UL];   // [b][l=100][c=3200]
__device__ __nv_bfloat16 g_xt_lo[81920000UL];

struct Params {
    const float* w[24];  // [mod][wq,wk,wv,bq,bk,bv]
};

// ---------------------------------------------------------------- helpers
__device__ __forceinline__ uint32_t smem_to_u32(const void* p) {
    uint32_t a;
    asm("{ .reg .u64 t; cvta.to.shared.u64 t, %1; cvt.u32.u64 %0, t; }" : "=r"(a) : "l"(p));
    return a;
}
__device__ __forceinline__ void ldsm4(uint32_t* r, uint32_t addr) {
    asm volatile("ldmatrix.sync.aligned.m8n8.x4.shared.b16 {%0,%1,%2,%3}, [%4];"
        : "=r"(r[0]), "=r"(r[1]), "=r"(r[2]), "=r"(r[3]) : "r"(addr));
}
__device__ __forceinline__ void ldsm2(uint32_t* r, uint32_t addr) {
    asm volatile("ldmatrix.sync.aligned.m8n8.x2.shared.b16 {%0,%1}, [%2];"
        : "=r"(r[0]), "=r"(r[1]) : "r"(addr));
}
__device__ __forceinline__ void mma16816(float* c, const uint32_t* a, uint32_t b0, uint32_t b1) {
    asm volatile("mma.sync.aligned.m16n8k16.row.col.f32.bf16.bf16.f32 "
        "{%0,%1,%2,%3}, {%4,%5,%6,%7}, {%8,%9}, {%0,%1,%2,%3};"
        : "+f"(c[0]), "+f"(c[1]), "+f"(c[2]), "+f"(c[3])
        : "r"(a[0]), "r"(a[1]), "r"(a[2]), "r"(a[3]), "r"(b0), "r"(b1));
}
__device__ __forceinline__ unsigned long long pack2(float x, float y) {
    unsigned long long r;
    asm("mov.b64 %0, {%1, %2};" : "=l"(r) : "f"(x), "f"(y));
    return r;
}
__device__ __forceinline__ void unpack2(unsigned long long v, float& x, float& y) {
    asm("mov.b64 {%0, %1}, %2;" : "=f"(x), "=f"(y) : "l"(v));
}
__device__ __forceinline__ void ffma2(unsigned long long& c, unsigned long long a, unsigned long long b) {
    asm("fma.rn.f32x2 %0, %1, %2, %0;" : "+l"(c) : "l"(a), "l"(b));
}
__device__ __forceinline__ unsigned long long lds_u64(uint32_t a) {
    unsigned long long v;
    asm volatile("ld.shared.b64 %0, [%1];" : "=l"(v) : "r"(a));
    return v;
}

// ============================================================================
// prep_w: fp32 weights -> bf16 hi/lo
// ============================================================================
__global__ void prep_w(Params p) {
    const int seg = blockIdx.y;
    const int mod = seg / 3;
    const int Cin = (mod == 1) ? 1280 : 640;
    const size_t offs[12] = {0, 409600, 819200, 1228800, 2048000, 2867200,
                             3686400, 4096000, 4505600, 4915200, 5324800, 5734400};
    const float* __restrict__ w = p.w[mod * 6 + (seg % 3)];
    const size_t off = offs[seg];
    const size_t n = (size_t)640 * Cin;
    for (size_t i = (size_t)blockIdx.x * blockDim.x + threadIdx.x; i < n; i += (size_t)gridDim.x * blockDim.x) {
        float v = w[i];
        __nv_bfloat16 h = __float2bfloat16(v);
        g_w_hi[off + i] = h;
        g_w_lo[off + i] = __float2bfloat16(v - __bfloat162float(h));
    }
}

// ============================================================================
// prep_x: x[b][C=3200][L=100] fp32 -> XT[b][l][c] bf16 hi/lo
// ============================================================================
__global__ void prep_x(const float* __restrict__ x) {
    __shared__ float t[32][33];
    const int b = blockIdx.z, ct = blockIdx.x, lt = blockIdx.y;
    const int tx = threadIdx.x, ty = threadIdx.y;
    const float* xb = x + (size_t)b * 320000;
    const int l = lt * 32 + tx;
    #pragma unroll
    for (int j = 0; j < 4; j++) {
        int c = ct * 32 + ty + j * 8;
        t[ty + j * 8][tx] = (l < 100) ? xb[(size_t)c * 100 + l] : 0.0f;
    }
    __syncthreads();
    const int c_out = ct * 32 + tx;
    const size_t xtb = (size_t)b * 320000;
    #pragma unroll
    for (int j = 0; j < 4; j++) {
        int lo_ = lt * 32 + ty + j * 8;
        if (lo_ < 100) {
            float v = t[tx][ty + j * 8];
            __nv_bfloat16 h = __float2bfloat16(v);
            size_t o = xtb + (size_t)lo_ * 3200 + c_out;
            g_xt_hi[o] = h;
            g_xt_lo[o] = __float2bfloat16(v - __bfloat162float(h));
        }
    }
}

// ============================================================================
// qkv_mma: unchanged (at mma.sync rate).
// ============================================================================
#define STAGE  37120u
#define OFF_AH 0u
#define OFF_AL 10240u
#define OFF_BH 20480u
#define OFF_BL 28800u

__global__ __launch_bounds__(256, 2) void qkv_mma(Params p) {
    extern __shared__ __align__(16) char smem_raw[];
    const uint32_t sb = smem_to_u32(smem_raw);

    const int tid = threadIdx.x;
    int bid = blockIdx.x;
    const int mtile = bid % 5; bid /= 5;
    const int proj  = bid % 3; bid /= 3;
    const int mod   = bid & 3;
    const int b     = bid >> 2;

    const int Cin = (mod == 1) ? 1280 : 640;
    const int nch = Cin >> 5;
    const int mbase = mtile * 128;

    const size_t offs[12] = {0, 409600, 819200, 1228800, 2048000, 2867200,
                             3686400, 4096000, 4505600, 4915200, 5324800, 5734400};
    const int c0m_tab[4] = {2560, 640, 1920, 0};
    const size_t woff = offs[mod * 3 + proj];
    const size_t xoff = (size_t)b * 320000 + c0m_tab[mod];
    const float* __restrict__ bias = p.w[mod * 6 + 3 + proj];
    float* __restrict__ O = g_scr + ((((size_t)b * 4 + mod) * 3 + proj) * 640 + mbase) * 100;

    const __nv_bfloat16* __restrict__ Wh = g_w_hi + woff;
    const __nv_bfloat16* __restrict__ Wl = g_w_lo + woff;
    const __nv_bfloat16* __restrict__ Xh = g_xt_hi + xoff;
    const __nv_bfloat16* __restrict__ Xl = g_xt_lo + xoff;

    for (int idx = tid; idx < 320; idx += 256) {
        int st = idx / 160, rest = idx % 160;
        int buf = rest / 80, r2 = rest % 80;
        uint32_t a = sb + (uint32_t)st * STAGE + (buf ? OFF_BL : OFF_BH)
                   + (uint32_t)(100 + r2 / 20) * 80 + (uint32_t)(r2 % 20) * 4;
        asm volatile("st.shared.b32 [%0], %1;" :: "r"(a), "r"(0) : "memory");
    }

    auto issue_chunk = [&](int st, int c) {
        const int k0 = c << 5;
        const uint32_t stg = sb + (uint32_t)st * STAGE;
        for (int idx = tid; idx < 1824; idx += 256) {
            const __nv_bfloat16* src;
            uint32_t dst;
            if (idx < 1024) {
                int buf = idx >> 9, r = (idx >> 2) & 127, seg = idx & 3;
                src = (buf ? Wl : Wh) + (size_t)(mbase + r) * Cin + k0 + seg * 8;
                dst = stg + (buf ? OFF_AL : OFF_AH) + (uint32_t)r * 80 + (uint32_t)seg * 16;
            } else {
                int j = idx - 1024;
                int n = j >> 3, rem = j & 7;
                int buf = rem >> 2, seg = rem & 3;
                src = (buf ? Xl : Xh) + (size_t)n * 3200 + k0 + seg * 8;
                dst = stg + (buf ? OFF_BL : OFF_BH) + (uint32_t)n * 80 + (uint32_t)seg * 16;
            }
            asm volatile("cp.async.cg.shared.global [%0], [%1], 16;" :: "r"(dst), "l"(src) : "memory");
        }
        asm volatile("cp.async.commit_group;" ::: "memory");
    };

    const int w = tid >> 5, lane = tid & 31;
    const int rloc = w * 16 + (lane >> 2);
    const int qd = lane & 3;

    const uint32_t aoff = (uint32_t)(w * 16 + (lane & 15)) * 80 + (uint32_t)(lane >> 4) * 16;
    const uint32_t b4off = (uint32_t)(((lane >> 4) * 8) + (lane & 7)) * 80 + (uint32_t)((lane >> 3) & 1) * 16;
    const uint32_t b2off = (uint32_t)(lane & 7) * 80 + (uint32_t)((lane >> 3) & 1) * 16;

    float acc[13][4];
    #pragma unroll
    for (int t = 0; t < 13; t++)
        #pragma unroll
        for (int i = 0; i < 4; i++) acc[t][i] = 0.0f;

    issue_chunk(0, 0);

    for (int c = 0; c < nch; c++) {
        const int s = c & 1;
        if (c + 1 < nch) {
            issue_chunk(s ^ 1, c + 1);
            asm volatile("cp.async.wait_group 1;" ::: "memory");
        } else {
            asm volatile("cp.async.wait_group 0;" ::: "memory");
        }
        __syncthreads();

        const uint32_t stg = sb + (uint32_t)s * STAGE;
        const uint32_t aAh = stg + OFF_AH + aoff;
        const uint32_t aAl = stg + OFF_AL + aoff;
        const uint32_t aBh4 = stg + OFF_BH + b4off;
        const uint32_t aBl4 = stg + OFF_BL + b4off;
        const uint32_t aBh2 = stg + OFF_BH + 7680u + b2off;
        const uint32_t aBl2 = stg + OFF_BL + 7680u + b2off;

        #pragma unroll
        for (int s16 = 0; s16 < 2; s16++) {
            const uint32_t ko = (uint32_t)s16 * 32;
            uint32_t ah[4], al[4];
            ldsm4(ah, aAh + ko);
            ldsm4(al, aAl + ko);
            #pragma unroll
            for (int pr = 0; pr < 6; pr++) {
                uint32_t bh[4], bl[4];
                ldsm4(bh, aBh4 + (uint32_t)pr * 1280 + ko);
                ldsm4(bl, aBl4 + (uint32_t)pr * 1280 + ko);
                mma16816(acc[2 * pr],     ah, bh[0], bh[1]);
                mma16816(acc[2 * pr + 1], ah, bh[2], bh[3]);
                mma16816(acc[2 * pr],     ah, bl[0], bl[1]);
                mma16816(acc[2 * pr + 1], ah, bl[2], bl[3]);
                mma16816(acc[2 * pr],     al, bh[0], bh[1]);
                mma16816(acc[2 * pr + 1], al, bh[2], bh[3]);
            }
            {
                uint32_t bh[2], bl[2];
                ldsm2(bh, aBh2 + ko);
                ldsm2(bl, aBl2 + ko);
                mma16816(acc[12], ah, bh[0], bh[1]);
                mma16816(acc[12], ah, bl[0], bl[1]);
                mma16816(acc[12], al, bh[0], bh[1]);
            }
        }
        __syncthreads();
    }

    const float bv0 = bias[mbase + rloc];
    const float bv1 = bias[mbase + rloc + 8];
    float* o0 = O + (size_t)rloc * 100;
    float* o1 = o0 + 800;
    #pragma unroll
    for (int t = 0; t < 13; t++) {
        int col = t * 8 + qd * 2;
        if (col < 100) {
            float2 v0 = make_float2(acc[t][0] + bv0, acc[t][1] + bv0);
            float2 v1 = make_float2(acc[t][2] + bv1, acc[t][3] + bv1);
            *(float2*)(o0 + col) = v0;
            *(float2*)(o1 + col) = v1;
        }
    }
}

// ============================================================================
// Pass 2: attention v4.  One CTA per (b,mod), 256 threads, 3 CTAs/SM.
// Smem (words): Pt[100][100] @0 | U @10000 (Qc/Kc 6656w, aliased Vc[64][100])
//               | part[100][10] @16656 | row[100] @17656.  Total 71040 B.
//   Phase A: 4l x 10m tile, S register-resident.
//   Softmax: smem partial reductions, exp in regs, transposed store to Pt.
//   Phase C: chunk 64 c-rows, 4c x 10i tile (160 threads), b64 Pt loads.
// ============================================================================
#define PT_OFF   0
#define U_OFF    10000
#define KC_OFF   3328
#define PART_OFF 16656
#define ROW_OFF  17656
#define ATTN_SMEM 71040

__global__ __launch_bounds__(256, 3) void attn_kernel(float* __restrict__ out) {
    extern __shared__ __align__(16) float sm[];
    const int tid = threadIdx.x;
    const int bm = blockIdx.x;           // b*4 + mod
    const int mod = bm & 3, b = bm >> 2;

    const float* __restrict__ Q = g_scr + (size_t)bm * 192000;
    const float* __restrict__ K = Q + 64000;
    const float* __restrict__ V = Q + 128000;
    float* __restrict__ O = out + ((size_t)mod * NB + b) * 64000;

    float* Pt   = sm + PT_OFF;           // [m][l], stride 100
    float* U    = sm + U_OFF;            // Qc stride 104; Kc at +KC_OFF stride 104; Vc stride 100
    float* part = sm + PART_OFF;         // [100][10]
    float* row  = sm + ROW_OFF;          // [100]
    const uint32_t u_b = smem_to_u32(U);
    const uint32_t pt_b = smem_to_u32(Pt);

    // ---- Phase A: S[100,100] = Q^T K, k-chunks of 32 ----
    const bool act = tid < 250;
    const int lg = tid % 25;             // l set {lg, lg+25, lg+50, lg+75}
    const int mg = tid / 25;             // 0..9 active
    const int m0 = mg * 10;

    unsigned long long acc[4][5];
    #pragma unroll
    for (int t = 0; t < 4; t++)
        #pragma unroll
        for (int j = 0; j < 5; j++) acc[t][j] = 0ULL;

    for (int c0 = 0; c0 < 640; c0 += 32) {
        for (int idx = tid; idx < 1600; idx += 256) {
            int which = idx >= 800;
            int i2 = idx - which * 800;
            int rw = i2 / 25, c4 = (i2 % 25) * 4;
            const float* src = (which ? K : Q) + (size_t)(c0 + rw) * 100 + c4;
            *(float4*)(U + which * KC_OFF + rw * 104 + c4) = *(const float4*)src;
        }
        __syncthreads();
        if (act) {
            #pragma unroll 2
            for (int kk = 0; kk < 32; kk++) {
                const float* qrow = U + kk * 104;
                unsigned long long qd_[4];
                #pragma unroll
                for (int t = 0; t < 4; t++) {
                    float qv = qrow[lg + 25 * t];
                    qd_[t] = pack2(qv, qv);
                }
                const uint32_t kb = u_b + (uint32_t)(KC_OFF + kk * 104 + m0) * 4;
                #pragma unroll
                for (int j = 0; j < 5; j++) {
                    unsigned long long kv = lds_u64(kb + (uint32_t)j * 8);
                    ffma2(acc[0][j], qd_[0], kv);
                    ffma2(acc[1][j], qd_[1], kv);
                    ffma2(acc[2][j], qd_[2], kv);
                    ffma2(acc[3][j], qd_[3], kv);
                }
            }
        }
        __syncthreads();
    }

    // ---- Softmax (register-resident S) ----
    if (act) {
        #pragma unroll
        for (int t = 0; t < 4; t++) {
            float mx = -3.4e38f;
            #pragma unroll
            for (int j = 0; j < 5; j++) {
                float lo, hi;
                unpack2(acc[t][j], lo, hi);
                mx = fmaxf(mx, fmaxf(lo, hi));
            }
            part[(lg + 25 * t) * 10 + mg] = mx;
        }
    }
    __syncthreads();
    if (tid < 100) {
        float m = -3.4e38f;
        #pragma unroll
        for (int g = 0; g < 10; g++) m = fmaxf(m, part[tid * 10 + g]);
        row[tid] = m;
    }
    __syncthreads();
    if (act) {
        #pragma unroll
        for (int t = 0; t < 4; t++) {
            float mr = row[lg + 25 * t];
            float s = 0.0f;
            #pragma unroll
            for (int j = 0; j < 5; j++) {
                float lo, hi;
                unpack2(acc[t][j], lo, hi);
                float e0 = __expf(lo - mr), e1 = __expf(hi - mr);
                s += e0 + e1;
                acc[t][j] = pack2(e0, e1);
            }
            part[(lg + 25 * t) * 10 + mg] = s;
        }
    }
    __syncthreads();
    if (tid < 100) {
        float s = 0.0f;
        #pragma unroll
        for (int g = 0; g < 10; g++) s += part[tid * 10 + g];
        row[tid] = 1.0f / s;
    }
    __syncthreads();
    if (act) {
        #pragma unroll
        for (int t = 0; t < 4; t++) {
            int l = lg + 25 * t;
            float inv = row[l];
            #pragma unroll
            for (int j = 0; j < 5; j++) {
                float lo, hi;
                unpack2(acc[t][j], lo, hi);
                int m = m0 + 2 * j;
                Pt[m * 100 + l]       = lo * inv;
                Pt[(m + 1) * 100 + l] = hi * inv;
            }
        }
    }

    // ---- Phase C: O[640,100] = V @ P^T, chunks of 64 c-rows ----
    const int cgC = tid % 16, igC = tid / 16;   // igC 0..15, active < 10
    const bool actC = igC < 10;
    const int i0 = igC * 10;

    for (int chunk = 0; chunk < 10; chunk++) {
        __syncthreads();                         // softmax done / prior Vc consumers done
        for (int idx = tid; idx < 1600; idx += 256) {
            int rw = idx / 25, c4 = (idx % 25) * 4;
            *(float4*)(U + rw * 100 + c4) =
                *(const float4*)(V + (size_t)(chunk * 64 + rw) * 100 + c4);
        }
        __syncthreads();
        if (actC) {
            unsigned long long pacc[4][5];
            #pragma unroll
            for (int u = 0; u < 4; u++)
                #pragma unroll
                for (int s = 0; s < 5; s++) pacc[u][s] = 0ULL;
            const uint32_t pb = pt_b + (uint32_t)i0 * 4;
            #pragma unroll 4
            for (int j = 0; j < 100; j++) {
                unsigned long long vd[4];
                #pragma unroll
                for (int u = 0; u < 4; u++) {
                    float vv = U[(cgC + 16 * u) * 100 + j];
                    vd[u] = pack2(vv, vv);
                }
                const uint32_t pj = pb + (uint32_t)j * 400;
                #pragma unroll
                for (int s = 0; s < 5; s++) {
                    unsigned long long pp = lds_u64(pj + (uint32_t)s * 8);
                    ffma2(pacc[0][s], vd[0], pp);
                    ffma2(pacc[1][s], vd[1], pp);
                    ffma2(pacc[2][s], vd[2], pp);
                    ffma2(pacc[3][s], vd[3], pp);
                }
            }
            #pragma unroll
            for (int u = 0; u < 4; u++) {
                int c_ = chunk * 64 + cgC + 16 * u;
                float* orow = O + (size_t)c_ * 100 + i0;
                #pragma unroll
                for (int s = 0; s < 5; s++) {
                    float a0, a1;
                    unpack2(pacc[u][s], a0, a1);
                    *(float2*)(orow + 2 * s) = make_float2(a0, a1);
                }
            }
        }
    }
}

extern "C" void kernel_launch(void* const* d_in, const int* in_sizes, int n_in,
                              void* d_out, int out_size) {
    const float* x = (const float*)d_in[0];
    Params p;
    for (int i = 0; i < 24; i++) p.w[i] = (const float*)d_in[1 + i];

    prep_w<<<dim3(800, 12), 256>>>(p);
    prep_x<<<dim3(100, 4, 256), dim3(32, 8)>>>(x);

    cudaFuncSetAttribute(qkv_mma, cudaFuncAttributeMaxDynamicSharedMemorySize, 74240);
    qkv_mma<<<15360, 256, 74240>>>(p);

    cudaFuncSetAttribute(attn_kernel, cudaFuncAttributeMaxDynamicSharedMemorySize, ATTN_SMEM);
    attn_kernel<<<1024, 256, ATTN_SMEM>>>((float*)d_out);
}